// round 11
// baseline (speedup 1.0000x reference)
#include <cuda_runtime.h>

// Gaussian-splat over-compositing, N pixels x K gaussians, sm_103a.
// R11: two-phase packed loop.
//  Phase 1 (exact, R3 semantics):
//   e = exp2(quad); w = e*omp; u = u*g_prev + col*w;
//   pan = pa+w; omp -= w; r = rcp(pan+eps); g = pan*r
//  Phase 2 (after ALL warp pixels have pa > 0.25; per-step factor
//   pa/(pa+eps) is within 4e-8 of 1, skipped):
//   e = exp2(quad); w = e*omp; u += col*w; omp -= w
//  Final: pa = 1-omp; pc = u * rcp(pa+eps).
// 2 px/thread packed f32x2, 64-thread blocks, grid ~2048.

#define MAXK 128

typedef unsigned long long u64;

__device__ __forceinline__ u64 pack2(float a, float b) {
    u64 r; asm("mov.b64 %0, {%1, %2};" : "=l"(r) : "f"(a), "f"(b)); return r;
}
__device__ __forceinline__ void unpack2(u64 v, float& a, float& b) {
    asm("mov.b64 {%0, %1}, %2;" : "=f"(a), "=f"(b) : "l"(v));
}
__device__ __forceinline__ u64 fma2(u64 a, u64 b, u64 c) {
    u64 d; asm("fma.rn.f32x2 %0, %1, %2, %3;" : "=l"(d) : "l"(a), "l"(b), "l"(c)); return d;
}
__device__ __forceinline__ u64 add2(u64 a, u64 b) {
    u64 d; asm("add.rn.f32x2 %0, %1, %2;" : "=l"(d) : "l"(a), "l"(b)); return d;
}
__device__ __forceinline__ u64 mul2(u64 a, u64 b) {
    u64 d; asm("mul.rn.f32x2 %0, %1, %2;" : "=l"(d) : "l"(a), "l"(b)); return d;
}
// paired MUFU in one asm block so ptxas can coalesce the pair moves
__device__ __forceinline__ u64 ex2_2(u64 q) {
    u64 e;
    asm("{\n\t.reg .f32 lo, hi;\n\t"
        "mov.b64 {lo, hi}, %1;\n\t"
        "ex2.approx.f32 lo, lo;\n\t"
        "ex2.approx.f32 hi, hi;\n\t"
        "mov.b64 %0, {lo, hi};\n\t}"
        : "=l"(e) : "l"(q));
    return e;
}
__device__ __forceinline__ u64 rcp_2(u64 d) {
    u64 r;
    asm("{\n\t.reg .f32 lo, hi;\n\t"
        "mov.b64 {lo, hi}, %1;\n\t"
        "rcp.approx.f32 lo, lo;\n\t"
        "rcp.approx.f32 hi, hi;\n\t"
        "mov.b64 %0, {lo, hi};\n\t}"
        : "=l"(r) : "l"(d));
    return r;
}
__device__ __forceinline__ float rcpf_(float x) {
    float y; asm("rcp.approx.f32 %0, %1;" : "=f"(y) : "f"(x)); return y;
}

// ---- shared param prep (identical math to R3, which passed) ----
__device__ __forceinline__ void prep_params(float2* sp,
                                            const float* mu, const float* alpha,
                                            const float* color, const float* scales,
                                            const float* thetas, int K) {
    const float L2E = 1.44269504088896340736f;
    for (int k = threadIdx.x; k < K; k += blockDim.x) {
        float th = thetas[k];
        float c = cosf(th), s = sinf(th);
        float sx = fmaxf(scales[2 * k + 0], 0.1f);
        float sy = fmaxf(scales[2 * k + 1], 0.1f);
        float ix = 1.0f / (sx * sx);
        float iy = 1.0f / (sy * sy);
        float S00 = c * c * ix + s * s * iy;
        float S01 = c * s * (ix - iy);
        float S11 = s * s * ix + c * c * iy;
        float h = -0.5f * L2E;
        float A  = h * S00;
        float B2 = (2.0f * h) * S01;
        float C  = h * S11;
        float a  = fminf(fmaxf(alpha[k], 0.0f), 1.0f);
        float la = log2f(fmaxf(a, 1e-38f));
        float c0 = fminf(fmaxf(color[3 * k + 0], 0.0f), 255.0f);
        float c1 = fminf(fmaxf(color[3 * k + 1], 0.0f), 255.0f);
        float c2 = fminf(fmaxf(color[3 * k + 2], 0.0f), 255.0f);
        float mx = mu[2 * k + 0] - 256.0f;   // centered
        float my = mu[2 * k + 1] - 256.0f;
        float Dx = -(2.0f * A * mx + B2 * my);
        float Ey = -(B2 * mx + 2.0f * C * my);
        float F  = (A * mx * mx + B2 * mx * my + C * my * my) + la;
        float2* p = &sp[k * 10];
        p[0] = make_float2(A, A);
        p[1] = make_float2(B2, B2);
        p[2] = make_float2(C, C);
        p[3] = make_float2(Dx, Dx);
        p[4] = make_float2(Ey, Ey);
        p[5] = make_float2(F, F);
        p[6] = make_float2(c0, c0);
        p[7] = make_float2(c1, c1);
        p[8] = make_float2(c2, c2);
        p[9] = make_float2(0.0f, 0.0f);
    }
}

template<int KT>
__global__ __launch_bounds__(64)
void gs_splat_kernel(const float* __restrict__ pos,
                     const float* __restrict__ mu,
                     const float* __restrict__ alpha,
                     const float* __restrict__ color,
                     const float* __restrict__ scales,
                     const float* __restrict__ thetas,
                     float4* __restrict__ out,
                     int n, int K)
{
    __shared__ __align__(16) float2 sp[MAXK * 10];
    prep_params(sp, mu, alpha, color, scales, thetas, K);
    __syncthreads();

    int base = blockIdx.x * ((int)blockDim.x * 2);
    int i0 = base + threadIdx.x;
    int i1 = i0 + blockDim.x;
    bool v0 = (i0 < n), v1 = (i1 < n);
    const float2* pos2 = (const float2*)pos;
    float2 P0 = v0 ? pos2[i0] : make_float2(0.0f, 0.0f);
    float2 P1 = v1 ? pos2[i1] : make_float2(0.0f, 0.0f);

    float ax = P0.x - 256.0f, ay = P0.y - 256.0f;
    float bx = P1.x - 256.0f, by = P1.y - 256.0f;
    u64 X  = pack2(ax, bx);
    u64 Y  = pack2(ay, by);
    u64 X2 = mul2(X, X);
    u64 XY = mul2(X, Y);
    u64 Y2 = mul2(Y, Y);

    u64 u0 = 0ull, u1 = 0ull, u2 = 0ull;   // scaled color numerators
    u64 pa = 0ull;                          // accumulated alpha (phase 1)
    u64 gC = 0ull;                          // carry factor pa/(pa+eps)
    u64 omp = pack2(1.0f, 1.0f);            // 1 - pa
    const u64 EPS2 = pack2(1e-8f, 1e-8f);
    const u64 NEG1 = pack2(-1.0f, -1.0f);

    const ulonglong2* __restrict__ g = (const ulonglong2*)sp;

    if (KT == 128) {
        int k = 0;
        // ---- phase 1: exact steps until whole warp saturates ----
        for (; k < 128; ) {
#pragma unroll
            for (int j = 0; j < 8; j++) {
                int kk = k + j;
                ulonglong2 g0 = g[kk * 5 + 0];
                ulonglong2 g1 = g[kk * 5 + 1];
                ulonglong2 g2 = g[kk * 5 + 2];
                ulonglong2 g3 = g[kk * 5 + 3];
                ulonglong2 g4 = g[kk * 5 + 4];

                u64 t = fma2(g2.x, Y, g2.y);
                t = fma2(g1.y, X, t);
                t = fma2(g1.x, Y2, t);
                t = fma2(g0.y, XY, t);
                u64 q = fma2(g0.x, X2, t);

                u64 e = ex2_2(q);
                u64 w = mul2(e, omp);
                u64 cw0 = mul2(g3.x, w);
                u64 cw1 = mul2(g3.y, w);
                u64 cw2 = mul2(g4.x, w);
                u0 = fma2(u0, gC, cw0);
                u1 = fma2(u1, gC, cw1);
                u2 = fma2(u2, gC, cw2);

                u64 pan = add2(pa, w);
                omp = fma2(w, NEG1, omp);
                u64 d = add2(pan, EPS2);
                u64 rc = rcp_2(d);
                gC = mul2(pan, rc);
                pa = pan;
            }
            k += 8;
            float a0, a1; unpack2(pa, a0, a1);
            if (__all_sync(0xffffffffu, fminf(a0, a1) > 0.25f)) break;
        }
        // ---- phase 2: cheap steps (skip g factor, err <= 4e-8/step) ----
        for (; k < 128; k += 8) {
#pragma unroll
            for (int j = 0; j < 8; j++) {
                int kk = k + j;
                ulonglong2 g0 = g[kk * 5 + 0];
                ulonglong2 g1 = g[kk * 5 + 1];
                ulonglong2 g2 = g[kk * 5 + 2];
                ulonglong2 g3 = g[kk * 5 + 3];
                ulonglong2 g4 = g[kk * 5 + 4];

                u64 t = fma2(g2.x, Y, g2.y);
                t = fma2(g1.y, X, t);
                t = fma2(g1.x, Y2, t);
                t = fma2(g0.y, XY, t);
                u64 q = fma2(g0.x, X2, t);

                u64 e = ex2_2(q);
                u64 w = mul2(e, omp);
                u0 = fma2(g3.x, w, u0);
                u1 = fma2(g3.y, w, u1);
                u2 = fma2(g4.x, w, u2);
                omp = fma2(w, NEG1, omp);
            }
        }
    } else {
        // generic exact loop (R10, passed @2.5e-6)
        u64 rC = 0ull;
#pragma unroll 4
        for (int k = 0; k < K; k++) {
            ulonglong2 g0 = g[k * 5 + 0];
            ulonglong2 g1 = g[k * 5 + 1];
            ulonglong2 g2 = g[k * 5 + 2];
            ulonglong2 g3 = g[k * 5 + 3];
            ulonglong2 g4 = g[k * 5 + 4];

            u64 t = fma2(g2.x, Y, g2.y);
            t = fma2(g1.y, X, t);
            t = fma2(g1.x, Y2, t);
            t = fma2(g0.y, XY, t);
            u64 q = fma2(g0.x, X2, t);

            u64 e = ex2_2(q);
            u64 w = mul2(e, omp);
            u64 cw0 = mul2(g3.x, w);
            u64 cw1 = mul2(g3.y, w);
            u64 cw2 = mul2(g4.x, w);
            u0 = fma2(u0, gC, cw0);
            u1 = fma2(u1, gC, cw1);
            u2 = fma2(u2, gC, cw2);

            u64 pan = add2(pa, w);
            omp = fma2(w, NEG1, omp);
            u64 d = add2(pan, EPS2);
            rC = rcp_2(d);
            gC = mul2(pan, rC);
            pa = pan;
        }
    }

    // ---- epilogue: pa = 1-omp; pc = u * rcp(pa+eps) ----
    float o0, o1;  unpack2(omp, o0, o1);
    float u00, u01; unpack2(u0, u00, u01);
    float u10, u11; unpack2(u1, u10, u11);
    float u20, u21; unpack2(u2, u20, u21);

    if (v0) {
        float paf = 1.0f - o0;
        float r = rcpf_(paf + 1e-8f);
        out[i0] = make_float4(fminf(fmaxf(u00 * r, 0.0f), 255.0f),
                              fminf(fmaxf(u10 * r, 0.0f), 255.0f),
                              fminf(fmaxf(u20 * r, 0.0f), 255.0f),
                              fminf(fmaxf(paf, 0.0f), 1.0f) * 255.0f);
    }
    if (v1) {
        float paf = 1.0f - o1;
        float r = rcpf_(paf + 1e-8f);
        out[i1] = make_float4(fminf(fmaxf(u01 * r, 0.0f), 255.0f),
                              fminf(fmaxf(u11 * r, 0.0f), 255.0f),
                              fminf(fmaxf(u21 * r, 0.0f), 255.0f),
                              fminf(fmaxf(paf, 0.0f), 1.0f) * 255.0f);
    }
}

extern "C" void kernel_launch(void* const* d_in, const int* in_sizes, int n_in,
                              void* d_out, int out_size)
{
    const float* pos    = (const float*)d_in[0];
    const float* mu     = (const float*)d_in[1];
    const float* alpha  = (const float*)d_in[2];
    const float* color  = (const float*)d_in[3];
    const float* scales = (const float*)d_in[4];
    const float* thetas = (const float*)d_in[5];

    int n = in_sizes[0] / 2;     // pixels
    int K = in_sizes[2];         // gaussians
    if (K > MAXK) K = MAXK;

    const int threads = 64;
    const int pixPerCta = threads * 2;   // 128 pixels per block
    int grid = (n + pixPerCta - 1) / pixPerCta;

    if (K == 128) {
        gs_splat_kernel<128><<<grid, threads>>>(pos, mu, alpha, color, scales,
                                                thetas, (float4*)d_out, n, K);
    } else {
        gs_splat_kernel<0><<<grid, threads>>>(pos, mu, alpha, color, scales,
                                              thetas, (float4*)d_out, n, K);
    }
}

// round 12
// speedup vs baseline: 1.0465x; 1.0465x over previous
#include <cuda_runtime.h>

// Gaussian-splat over-compositing, N pixels x K gaussians, sm_103a.
// R12: two-phase packed loop with a provable gate.
//  Phase 1 (exact R3 semantics):
//   e = exp2(quad); w = e*omp; u = u*g_prev + col*w;
//   pan = pa+w; omp -= w; r = rcp(pan+eps); g = pan*r
//  Phase 2 entered when ALL 64 warp pixels have pa > 0.02 (checked per 8
//   steps). Skipped factor g = 1 - eps/(pa+eps) errs <= 5e-7/step there
//   (pa monotone), <= 6.4e-5 total:
//   e = exp2(quad); w = e*omp; u += col*w; omp -= w
//  Final: pa = 1-omp; pc = u * rcp(pa+eps).
// 2 px/thread packed f32x2, 64-thread blocks.

#define MAXK 128

typedef unsigned long long u64;

__device__ __forceinline__ u64 pack2(float a, float b) {
    u64 r; asm("mov.b64 %0, {%1, %2};" : "=l"(r) : "f"(a), "f"(b)); return r;
}
__device__ __forceinline__ void unpack2(u64 v, float& a, float& b) {
    asm("mov.b64 {%0, %1}, %2;" : "=f"(a), "=f"(b) : "l"(v));
}
__device__ __forceinline__ u64 fma2(u64 a, u64 b, u64 c) {
    u64 d; asm("fma.rn.f32x2 %0, %1, %2, %3;" : "=l"(d) : "l"(a), "l"(b), "l"(c)); return d;
}
__device__ __forceinline__ u64 add2(u64 a, u64 b) {
    u64 d; asm("add.rn.f32x2 %0, %1, %2;" : "=l"(d) : "l"(a), "l"(b)); return d;
}
__device__ __forceinline__ u64 mul2(u64 a, u64 b) {
    u64 d; asm("mul.rn.f32x2 %0, %1, %2;" : "=l"(d) : "l"(a), "l"(b)); return d;
}
__device__ __forceinline__ u64 ex2_2(u64 q) {
    u64 e;
    asm("{\n\t.reg .f32 lo, hi;\n\t"
        "mov.b64 {lo, hi}, %1;\n\t"
        "ex2.approx.f32 lo, lo;\n\t"
        "ex2.approx.f32 hi, hi;\n\t"
        "mov.b64 %0, {lo, hi};\n\t}"
        : "=l"(e) : "l"(q));
    return e;
}
__device__ __forceinline__ u64 rcp_2(u64 d) {
    u64 r;
    asm("{\n\t.reg .f32 lo, hi;\n\t"
        "mov.b64 {lo, hi}, %1;\n\t"
        "rcp.approx.f32 lo, lo;\n\t"
        "rcp.approx.f32 hi, hi;\n\t"
        "mov.b64 %0, {lo, hi};\n\t}"
        : "=l"(r) : "l"(d));
    return r;
}
__device__ __forceinline__ float rcpf_(float x) {
    float y; asm("rcp.approx.f32 %0, %1;" : "=f"(y) : "f"(x)); return y;
}

// ---- shared param prep (identical math to R3, which passed) ----
__device__ __forceinline__ void prep_params(float2* sp,
                                            const float* mu, const float* alpha,
                                            const float* color, const float* scales,
                                            const float* thetas, int K) {
    const float L2E = 1.44269504088896340736f;
    for (int k = threadIdx.x; k < K; k += blockDim.x) {
        float th = thetas[k];
        float c = cosf(th), s = sinf(th);
        float sx = fmaxf(scales[2 * k + 0], 0.1f);
        float sy = fmaxf(scales[2 * k + 1], 0.1f);
        float ix = 1.0f / (sx * sx);
        float iy = 1.0f / (sy * sy);
        float S00 = c * c * ix + s * s * iy;
        float S01 = c * s * (ix - iy);
        float S11 = s * s * ix + c * c * iy;
        float h = -0.5f * L2E;
        float A  = h * S00;
        float B2 = (2.0f * h) * S01;
        float C  = h * S11;
        float a  = fminf(fmaxf(alpha[k], 0.0f), 1.0f);
        float la = log2f(fmaxf(a, 1e-38f));
        float c0 = fminf(fmaxf(color[3 * k + 0], 0.0f), 255.0f);
        float c1 = fminf(fmaxf(color[3 * k + 1], 0.0f), 255.0f);
        float c2 = fminf(fmaxf(color[3 * k + 2], 0.0f), 255.0f);
        float mx = mu[2 * k + 0] - 256.0f;   // centered
        float my = mu[2 * k + 1] - 256.0f;
        float Dx = -(2.0f * A * mx + B2 * my);
        float Ey = -(B2 * mx + 2.0f * C * my);
        float F  = (A * mx * mx + B2 * mx * my + C * my * my) + la;
        float2* p = &sp[k * 10];
        p[0] = make_float2(A, A);
        p[1] = make_float2(B2, B2);
        p[2] = make_float2(C, C);
        p[3] = make_float2(Dx, Dx);
        p[4] = make_float2(Ey, Ey);
        p[5] = make_float2(F, F);
        p[6] = make_float2(c0, c0);
        p[7] = make_float2(c1, c1);
        p[8] = make_float2(c2, c2);
        p[9] = make_float2(0.0f, 0.0f);
    }
}

template<int KT>
__global__ __launch_bounds__(64)
void gs_splat_kernel(const float* __restrict__ pos,
                     const float* __restrict__ mu,
                     const float* __restrict__ alpha,
                     const float* __restrict__ color,
                     const float* __restrict__ scales,
                     const float* __restrict__ thetas,
                     float4* __restrict__ out,
                     int n, int K)
{
    __shared__ __align__(16) float2 sp[MAXK * 10];
    prep_params(sp, mu, alpha, color, scales, thetas, K);
    __syncthreads();

    int base = blockIdx.x * ((int)blockDim.x * 2);
    int i0 = base + threadIdx.x;
    int i1 = i0 + blockDim.x;
    bool v0 = (i0 < n), v1 = (i1 < n);
    const float2* pos2 = (const float2*)pos;
    float2 P0 = v0 ? pos2[i0] : make_float2(0.0f, 0.0f);
    float2 P1 = v1 ? pos2[i1] : make_float2(0.0f, 0.0f);

    float ax = P0.x - 256.0f, ay = P0.y - 256.0f;
    float bx = P1.x - 256.0f, by = P1.y - 256.0f;
    u64 X  = pack2(ax, bx);
    u64 Y  = pack2(ay, by);
    u64 X2 = mul2(X, X);
    u64 XY = mul2(X, Y);
    u64 Y2 = mul2(Y, Y);

    u64 u0 = 0ull, u1 = 0ull, u2 = 0ull;   // scaled color numerators
    u64 pa = 0ull;                          // accumulated alpha (phase 1)
    u64 gC = 0ull;                          // carry factor pa/(pa+eps)
    u64 omp = pack2(1.0f, 1.0f);            // 1 - pa
    const u64 EPS2 = pack2(1e-8f, 1e-8f);
    const u64 NEG1 = pack2(-1.0f, -1.0f);

    const ulonglong2* __restrict__ g = (const ulonglong2*)sp;

    if (KT == 128) {
        int k = 0;
        // ---- phase 1: exact steps until the whole warp clears pa > 0.02 ----
        for (; k < 128; ) {
#pragma unroll
            for (int j = 0; j < 8; j++) {
                int kk = k + j;
                ulonglong2 g0 = g[kk * 5 + 0];
                ulonglong2 g1 = g[kk * 5 + 1];
                ulonglong2 g2 = g[kk * 5 + 2];
                ulonglong2 g3 = g[kk * 5 + 3];
                ulonglong2 g4 = g[kk * 5 + 4];

                u64 t = fma2(g2.x, Y, g2.y);
                t = fma2(g1.y, X, t);
                t = fma2(g1.x, Y2, t);
                t = fma2(g0.y, XY, t);
                u64 q = fma2(g0.x, X2, t);

                u64 e = ex2_2(q);
                u64 w = mul2(e, omp);
                u64 cw0 = mul2(g3.x, w);
                u64 cw1 = mul2(g3.y, w);
                u64 cw2 = mul2(g4.x, w);
                u0 = fma2(u0, gC, cw0);
                u1 = fma2(u1, gC, cw1);
                u2 = fma2(u2, gC, cw2);

                u64 pan = add2(pa, w);
                omp = fma2(w, NEG1, omp);
                u64 d = add2(pan, EPS2);
                u64 rc = rcp_2(d);
                gC = mul2(pan, rc);
                pa = pan;
            }
            k += 8;
            float a0, a1; unpack2(pa, a0, a1);
            if (__all_sync(0xffffffffu, fminf(a0, a1) > 0.02f)) break;
        }
        // ---- phase 2: cheap steps (g within 5e-7 of 1, skipped) ----
        for (; k < 128; k += 8) {
#pragma unroll
            for (int j = 0; j < 8; j++) {
                int kk = k + j;
                ulonglong2 g0 = g[kk * 5 + 0];
                ulonglong2 g1 = g[kk * 5 + 1];
                ulonglong2 g2 = g[kk * 5 + 2];
                ulonglong2 g3 = g[kk * 5 + 3];
                ulonglong2 g4 = g[kk * 5 + 4];

                u64 t = fma2(g2.x, Y, g2.y);
                t = fma2(g1.y, X, t);
                t = fma2(g1.x, Y2, t);
                t = fma2(g0.y, XY, t);
                u64 q = fma2(g0.x, X2, t);

                u64 e = ex2_2(q);
                u64 w = mul2(e, omp);
                u0 = fma2(g3.x, w, u0);
                u1 = fma2(g3.y, w, u1);
                u2 = fma2(g4.x, w, u2);
                omp = fma2(w, NEG1, omp);
            }
        }
    } else {
        // generic exact loop (R10, passed @2.5e-6)
#pragma unroll 4
        for (int k = 0; k < K; k++) {
            ulonglong2 g0 = g[k * 5 + 0];
            ulonglong2 g1 = g[k * 5 + 1];
            ulonglong2 g2 = g[k * 5 + 2];
            ulonglong2 g3 = g[k * 5 + 3];
            ulonglong2 g4 = g[k * 5 + 4];

            u64 t = fma2(g2.x, Y, g2.y);
            t = fma2(g1.y, X, t);
            t = fma2(g1.x, Y2, t);
            t = fma2(g0.y, XY, t);
            u64 q = fma2(g0.x, X2, t);

            u64 e = ex2_2(q);
            u64 w = mul2(e, omp);
            u64 cw0 = mul2(g3.x, w);
            u64 cw1 = mul2(g3.y, w);
            u64 cw2 = mul2(g4.x, w);
            u0 = fma2(u0, gC, cw0);
            u1 = fma2(u1, gC, cw1);
            u2 = fma2(u2, gC, cw2);

            u64 pan = add2(pa, w);
            omp = fma2(w, NEG1, omp);
            u64 d = add2(pan, EPS2);
            u64 rc = rcp_2(d);
            gC = mul2(pan, rc);
            pa = pan;
        }
    }

    // ---- epilogue: pa = 1-omp; pc = u * rcp(pa+eps) ----
    float o0, o1;  unpack2(omp, o0, o1);
    float u00, u01; unpack2(u0, u00, u01);
    float u10, u11; unpack2(u1, u10, u11);
    float u20, u21; unpack2(u2, u20, u21);

    if (v0) {
        float paf = 1.0f - o0;
        float r = rcpf_(paf + 1e-8f);
        out[i0] = make_float4(fminf(fmaxf(u00 * r, 0.0f), 255.0f),
                              fminf(fmaxf(u10 * r, 0.0f), 255.0f),
                              fminf(fmaxf(u20 * r, 0.0f), 255.0f),
                              fminf(fmaxf(paf, 0.0f), 1.0f) * 255.0f);
    }
    if (v1) {
        float paf = 1.0f - o1;
        float r = rcpf_(paf + 1e-8f);
        out[i1] = make_float4(fminf(fmaxf(u01 * r, 0.0f), 255.0f),
                              fminf(fmaxf(u11 * r, 0.0f), 255.0f),
                              fminf(fmaxf(u21 * r, 0.0f), 255.0f),
                              fminf(fmaxf(paf, 0.0f), 1.0f) * 255.0f);
    }
}

extern "C" void kernel_launch(void* const* d_in, const int* in_sizes, int n_in,
                              void* d_out, int out_size)
{
    const float* pos    = (const float*)d_in[0];
    const float* mu     = (const float*)d_in[1];
    const float* alpha  = (const float*)d_in[2];
    const float* color  = (const float*)d_in[3];
    const float* scales = (const float*)d_in[4];
    const float* thetas = (const float*)d_in[5];

    int n = in_sizes[0] / 2;     // pixels
    int K = in_sizes[2];         // gaussians
    if (K > MAXK) K = MAXK;

    const int threads = 64;
    const int pixPerCta = threads * 2;   // 128 pixels per block
    int grid = (n + pixPerCta - 1) / pixPerCta;

    if (K == 128) {
        gs_splat_kernel<128><<<grid, threads>>>(pos, mu, alpha, color, scales,
                                                thetas, (float4*)d_out, n, K);
    } else {
        gs_splat_kernel<0><<<grid, threads>>>(pos, mu, alpha, color, scales,
                                              thetas, (float4*)d_out, n, K);
    }
}

// round 13
// speedup vs baseline: 1.0617x; 1.0146x over previous
#include <cuda_runtime.h>

// Gaussian-splat over-compositing, N pixels x K gaussians, sm_103a.
// R13: SCALAR loop, 1 px/thread. No f32x2 packing -> no mov.b64 tax, and
// 2x warps (13.8/SMSP) for latency cover. Exact reference semantics via
// d = pa + eps as state:
//   om = 1 - d            (== 1-pa-eps, rel err 1e-8 on omp)
//   w  = e * om,  e = exp2(A x2 + B2 xy + C y2 + Dx x + Ey y + F)
//   u_c = u_c * g + c_c * w      (g from previous step)
//   d += w;  r = rcp(d);  g = 1 - eps*r   (== (d-eps)/d = pa/(pa+eps))
// Final: pa = d - eps; pc = u * r_last; alpha = clamp(pa,0,1)*255.
// 15 FFMA + 2 MUFU + 3 LDS.128 per px-step.

#define MAXK 128
#define EPSC 1e-8f

__device__ __forceinline__ float ex2f_(float x) {
    float y; asm("ex2.approx.f32 %0, %1;" : "=f"(y) : "f"(x)); return y;
}
__device__ __forceinline__ float rcpf_(float x) {
    float y; asm("rcp.approx.f32 %0, %1;" : "=f"(y) : "f"(x)); return y;
}

// ---- shared param prep (same math as R3/R10, passed @2.5e-6) ----
// layout per k: [A, B2, C, Dx] [Ey, F, c0, c1] [c2, 0, 0, 0]  (3 x float4)
__device__ __forceinline__ void prep_params(float4* sp4,
                                            const float* mu, const float* alpha,
                                            const float* color, const float* scales,
                                            const float* thetas, int K) {
    const float L2E = 1.44269504088896340736f;
    for (int k = threadIdx.x; k < K; k += blockDim.x) {
        float th = thetas[k];
        float c = cosf(th), s = sinf(th);
        float sx = fmaxf(scales[2 * k + 0], 0.1f);
        float sy = fmaxf(scales[2 * k + 1], 0.1f);
        float ix = 1.0f / (sx * sx);
        float iy = 1.0f / (sy * sy);
        float S00 = c * c * ix + s * s * iy;
        float S01 = c * s * (ix - iy);
        float S11 = s * s * ix + c * c * iy;
        float h = -0.5f * L2E;
        float A  = h * S00;
        float B2 = (2.0f * h) * S01;
        float C  = h * S11;
        float a  = fminf(fmaxf(alpha[k], 0.0f), 1.0f);
        float la = log2f(fmaxf(a, 1e-38f));
        float c0 = fminf(fmaxf(color[3 * k + 0], 0.0f), 255.0f);
        float c1 = fminf(fmaxf(color[3 * k + 1], 0.0f), 255.0f);
        float c2 = fminf(fmaxf(color[3 * k + 2], 0.0f), 255.0f);
        float mx = mu[2 * k + 0] - 256.0f;   // centered coords
        float my = mu[2 * k + 1] - 256.0f;
        float Dx = -(2.0f * A * mx + B2 * my);
        float Ey = -(B2 * mx + 2.0f * C * my);
        float F  = (A * mx * mx + B2 * mx * my + C * my * my) + la;
        sp4[k * 3 + 0] = make_float4(A, B2, C, Dx);
        sp4[k * 3 + 1] = make_float4(Ey, F, c0, c1);
        sp4[k * 3 + 2] = make_float4(c2, 0.0f, 0.0f, 0.0f);
    }
}

template<int KT>
__global__ __launch_bounds__(128)
void gs_splat_kernel(const float* __restrict__ pos,
                     const float* __restrict__ mu,
                     const float* __restrict__ alpha,
                     const float* __restrict__ color,
                     const float* __restrict__ scales,
                     const float* __restrict__ thetas,
                     float4* __restrict__ out,
                     int n, int K)
{
    const int KK = (KT > 0) ? KT : K;
    __shared__ __align__(16) float4 sp4[MAXK * 3];
    prep_params(sp4, mu, alpha, color, scales, thetas, K);
    __syncthreads();

    int i = blockIdx.x * blockDim.x + threadIdx.x;
    bool valid = (i < n);
    const float2* pos2 = (const float2*)pos;
    float2 P = valid ? pos2[i] : make_float2(0.0f, 0.0f);

    float X = P.x - 256.0f;
    float Y = P.y - 256.0f;
    float X2 = X * X;
    float XY = X * Y;
    float Y2 = Y * Y;

    float u0 = 0.0f, u1 = 0.0f, u2 = 0.0f;   // scaled color numerators
    float d  = EPSC;                          // pa + eps
    float gC = 0.0f;                          // carry factor pa/(pa+eps)
    float rC = 0.0f;                          // last rcp(d)

#pragma unroll 8
    for (int k = 0; k < KK; k++) {
        float4 p0 = sp4[k * 3 + 0];   // A, B2, C, Dx
        float4 p1 = sp4[k * 3 + 1];   // Ey, F, c0, c1
        float4 p2 = sp4[k * 3 + 2];   // c2, -, -, -

        float t = fmaf(p1.x, Y, p1.y);     // Ey*y + F
        t = fmaf(p0.w, X, t);              // + Dx*x
        t = fmaf(p0.z, Y2, t);             // + C*y2
        t = fmaf(p0.y, XY, t);             // + B2*xy
        float q = fmaf(p0.x, X2, t);       // + A*x2

        float e = ex2f_(q);                // alpha_k * gaussian

        float om = 1.0f - d;               // 1 - pa - eps
        float w  = e * om;                 // contribution weight
        u0 = fmaf(u0, gC, p1.z * w);       // u = u*g_prev + col*w
        u1 = fmaf(u1, gC, p1.w * w);
        u2 = fmaf(u2, gC, p2.x * w);

        d += w;                            // new pa + eps
        rC = rcpf_(d);
        gC = fmaf(rC, -EPSC, 1.0f);        // (d-eps)/d = pa/(pa+eps)
    }

    if (valid) {
        float pa = d - EPSC;
        out[i] = make_float4(fminf(fmaxf(u0 * rC, 0.0f), 255.0f),
                             fminf(fmaxf(u1 * rC, 0.0f), 255.0f),
                             fminf(fmaxf(u2 * rC, 0.0f), 255.0f),
                             fminf(fmaxf(pa, 0.0f), 1.0f) * 255.0f);
    }
}

extern "C" void kernel_launch(void* const* d_in, const int* in_sizes, int n_in,
                              void* d_out, int out_size)
{
    const float* pos    = (const float*)d_in[0];
    const float* mu     = (const float*)d_in[1];
    const float* alpha  = (const float*)d_in[2];
    const float* color  = (const float*)d_in[3];
    const float* scales = (const float*)d_in[4];
    const float* thetas = (const float*)d_in[5];

    int n = in_sizes[0] / 2;     // pixels
    int K = in_sizes[2];         // gaussians
    if (K > MAXK) K = MAXK;

    const int threads = 128;
    int grid = (n + threads - 1) / threads;

    if (K == 128) {
        gs_splat_kernel<128><<<grid, threads>>>(pos, mu, alpha, color, scales,
                                                thetas, (float4*)d_out, n, K);
    } else {
        gs_splat_kernel<0><<<grid, threads>>>(pos, mu, alpha, color, scales,
                                              thetas, (float4*)d_out, n, K);
    }
}